// round 4
// baseline (speedup 1.0000x reference)
#include <cuda_runtime.h>

#define D 2048
#define B 16

#define NGBLK   64      // gates worker blocks
#define GRID    296     // 148 SMs x 2 resident blocks
#define WITEMS  4096    // 16 slices x 16 batches x 16 row-chunks

// Scratch + sync state (allocation-free rule: device globals, zero-init)
__device__ float    g_u[B * D];
__device__ float    g_diag[B * D];
__device__ unsigned g_ready[16];
__device__ unsigned g_witem;
__device__ unsigned g_done;

__device__ __forceinline__ float sigmoidf(float x) {
    return 1.0f / (1.0f + __expf(-x));
}

// Warp transpose-reduce: lane l ends with (in v[0]) the 32-lane total of
// logical index l.
__device__ __forceinline__ void treduce32(float (&v)[32], int lane) {
#pragma unroll
    for (int m = 16; m > 0; m >>= 1) {
#pragma unroll
        for (int t = 0; t < 16; t++) {
            if (t < m) {
                float lo = v[t];
                float hi = v[t + m];
                float send = (lane & m) ? lo : hi;
                float recv = __shfl_xor_sync(0xffffffffu, send, m);
                v[t] = (lane & m) ? (hi + recv) : (lo + recv);
            }
        }
    }
}

__device__ __forceinline__ void finalize_one(
    int b, int i, float dA, float dX,
    const float* __restrict__ xt, const float* __restrict__ h,
    const float* __restrict__ ba, const float* __restrict__ bx,
    const float* __restrict__ Lam)
{
    float rt = sigmoidf(dA + __ldg(ba + i));
    float it = sigmoidf(dX + __ldg(bx + i));
    float la = -log1pf(__expf(-__ldg(Lam + i)));   // -softplus(-Lam)
    float t  = la * rt * 0.125f;                   // /C, C=8
    float a  = __expf(t);
    float om = -expm1f(2.0f * t);                  // 1 - a^2, cancellation-free
    float u  = sqrtf(fmaxf(om, 0.0f)) * it * __ldg(xt + b * D + i);
    g_u[b * D + i]    = u;
    g_diag[b * D + i] = a * __ldg(h + b * D + i);
}

// One gates item = 8 columns [ibase, ibase+8) x both matrices x all batches.
// Warp w: column pair ibase + (w&3)*2, batch group w>>2. All 256 threads.
__device__ void gates_item(
    int ibase, int tid, float4* xs4,
    const float* __restrict__ xt, const float* __restrict__ h,
    const float* __restrict__ Wa, const float* __restrict__ Wx,
    const float* __restrict__ ba, const float* __restrict__ bx,
    const float* __restrict__ Lam)
{
    const int lane = tid & 31;
    const int warp = tid >> 5;
    const int bg   = warp >> 2;
    const int i0   = ibase + (warp & 3) * 2;
    const int i1   = i0 + 1;

    // [0..7]=dotA(i0,b), [8..15]=dotX(i0,b), [16..23]=dotA(i1,b), [24..31]=dotX(i1,b)
    float v[32];
#pragma unroll
    for (int t = 0; t < 32; t++) v[t] = 0.0f;

    const float4* xt4 = reinterpret_cast<const float4*>(xt);

#pragma unroll 1
    for (int kt = 0; kt < D; kt += 512) {
        __syncthreads();
#pragma unroll
        for (int e = tid; e < B * 128; e += 256) {
            int b = e >> 7, c = e & 127;
            xs4[e] = xt4[b * (D / 4) + (kt >> 2) + c];
        }
        __syncthreads();

        const float4* wa0p = reinterpret_cast<const float4*>(Wa + (size_t)i0 * D + kt);
        const float4* wa1p = reinterpret_cast<const float4*>(Wa + (size_t)i1 * D + kt);
        const float4* wx0p = reinterpret_cast<const float4*>(Wx + (size_t)i0 * D + kt);
        const float4* wx1p = reinterpret_cast<const float4*>(Wx + (size_t)i1 * D + kt);
        const float4* xbase = xs4 + bg * 8 * 128;

#pragma unroll
        for (int m = 0; m < 4; m++) {
            const int idx = m * 32 + lane;
            float4 wa0 = __ldg(wa0p + idx);
            float4 wa1 = __ldg(wa1p + idx);
            float4 wx0 = __ldg(wx0p + idx);
            float4 wx1 = __ldg(wx1p + idx);
#pragma unroll
            for (int b = 0; b < 8; b++) {
                float4 x = xbase[b * 128 + idx];

                v[b]      = fmaf(wa0.x, x.x, v[b]);
                v[b]      = fmaf(wa0.y, x.y, v[b]);
                v[b]      = fmaf(wa0.z, x.z, v[b]);
                v[b]      = fmaf(wa0.w, x.w, v[b]);

                v[8 + b]  = fmaf(wx0.x, x.x, v[8 + b]);
                v[8 + b]  = fmaf(wx0.y, x.y, v[8 + b]);
                v[8 + b]  = fmaf(wx0.z, x.z, v[8 + b]);
                v[8 + b]  = fmaf(wx0.w, x.w, v[8 + b]);

                v[16 + b] = fmaf(wa1.x, x.x, v[16 + b]);
                v[16 + b] = fmaf(wa1.y, x.y, v[16 + b]);
                v[16 + b] = fmaf(wa1.z, x.z, v[16 + b]);
                v[16 + b] = fmaf(wa1.w, x.w, v[16 + b]);

                v[24 + b] = fmaf(wx1.x, x.x, v[24 + b]);
                v[24 + b] = fmaf(wx1.y, x.y, v[24 + b]);
                v[24 + b] = fmaf(wx1.z, x.z, v[24 + b]);
                v[24 + b] = fmaf(wx1.w, x.w, v[24 + b]);
            }
        }
    }

    treduce32(v, lane);
    float r = v[0];
    float p = __shfl_xor_sync(0xffffffffu, r, 8);   // pair dotA with dotX

    if (lane < 8) {
        finalize_one(bg * 8 + lane, i0, r, p, xt, h, ba, bx, Lam);
    } else if (lane >= 16 && lane < 24) {
        finalize_one(bg * 8 + (lane - 16), i1, r, p, xt, h, ba, bx, Lam);
    }
}

// Fused persistent kernel: gates producers + writer consumers with
// per-column-slice readiness flags. Writer item m (slice-major):
// s = m>>8, b = (m>>4)&15, ic = m&15 -> writes out[b, ic*128..+128, s*128..+128).
__global__ __launch_bounds__(256, 2) void fused_kernel(
    const float* __restrict__ xt, const float* __restrict__ h,
    const float* __restrict__ Wa, const float* __restrict__ Wx,
    const float* __restrict__ ba, const float* __restrict__ bx,
    const float* __restrict__ Lam, float* __restrict__ out)
{
    __shared__ float4   xs4[B * 128];   // 32 KB
    __shared__ unsigned s_item;

    const int tid  = threadIdx.x;
    const int bid  = blockIdx.x;
    const int lane = tid & 31;
    const int warp = tid >> 5;

    // ---------------- gates producer phase (blocks 0..63) ----------------
    if (bid < NGBLK) {
#pragma unroll 1
        for (int p = 0; p < 4; p++) {
            const int slice = 4 * p + (bid >> 4);   // phase p covers slices 4p..4p+3
            const int idx   = bid & 15;
            gates_item(slice * 128 + idx * 8, tid, xs4, xt, h, Wa, Wx, ba, bx, Lam);
            __threadfence();        // make u/diag visible device-wide (per writer thread)
            __syncthreads();
            if (tid == 0) atomicAdd(&g_ready[slice], 1u);
        }
    }

    // ---------------- writer consumer phase (all blocks) ----------------
    for (;;) {
        __syncthreads();                         // all readers done with s_item
        if (tid == 0) s_item = atomicAdd(&g_witem, 1u);
        __syncthreads();
        const unsigned m = s_item;
        if (m >= WITEMS) break;

        const int s  = m >> 8;
        const int b  = (m >> 4) & 15;
        const int ic = m & 15;

        if (tid == 0) {
            while (atomicAdd(&g_ready[s], 0u) < 16u) __nanosleep(64);
        }
        __syncthreads();
        __threadfence();                         // acquire side

        // u segment for this slice: 128 floats, one float4 per lane
        const float4 uv = *(reinterpret_cast<const float4*>(
                              g_u + (size_t)b * D + s * 128) + lane);

        // warp r writes rows ic*128 + r, +8, ... (16 rows)
        const float* dgb = g_diag + (size_t)b * D;
        float* rowp = out + ((size_t)b * D + (size_t)ic * 128 + warp) * D + s * 128;
        int i = ic * 128 + warp;

#pragma unroll 4
        for (int t = 0; t < 16; t++) {
            float4 val = uv;
            if (s == ic) {                        // diagonal lives in this tile
                int li = i - s * 128;             // 0..127
                if ((li >> 2) == lane) {
                    float dv = __ldg(dgb + i);
                    switch (li & 3) {
                        case 0: val.x += dv; break;
                        case 1: val.y += dv; break;
                        case 2: val.z += dv; break;
                        default: val.w += dv; break;
                    }
                }
            }
            __stcs(reinterpret_cast<float4*>(rowp) + lane, val);
            rowp += 8 * D;
            i    += 8;
        }
    }

    // ---------------- epilogue: last block resets sync state ----------------
    __syncthreads();
    if (tid == 0) {
        __threadfence();
        unsigned old = atomicAdd(&g_done, 1u);
        if (old == gridDim.x - 1) {
#pragma unroll
            for (int k = 0; k < 16; k++) g_ready[k] = 0u;
            g_witem = 0u;
            g_done  = 0u;
            __threadfence();
        }
    }
}

extern "C" void kernel_launch(void* const* d_in, const int* in_sizes, int n_in,
                              void* d_out, int out_size) {
    const float* xt  = (const float*)d_in[0];
    const float* h   = (const float*)d_in[1];
    const float* Wa  = (const float*)d_in[2];
    const float* Wx  = (const float*)d_in[3];
    const float* ba  = (const float*)d_in[4];
    const float* bx  = (const float*)d_in[5];
    const float* Lam = (const float*)d_in[6];

    fused_kernel<<<GRID, 256>>>(xt, h, Wa, Wx, ba, bx, Lam, (float*)d_out);
}